// round 10
// baseline (speedup 1.0000x reference)
#include <cuda_runtime.h>
#include <cuda_bf16.h>
#include <math.h>
#include <stdint.h>

#define Nn 8192
#define Mm 2048
#define Dd 32
#define STILES (Nn / 16)        // 512 sample tiles (m16)
#define MTILES (Mm / 8)         // 256 mean tiles (n8)
#define KSLOTS 8                // 4 hi + 4 lo k16-groups (dedup'd)
#define MB 16                   // mean blocks of 128
#define TBLOCKS 16

// Fragment-layout operands + scratch
__device__ __align__(16) uint32_t g_Afrag[STILES * KSLOTS * 32 * 4]; // uint4/slot
__device__ __align__(16) uint32_t g_Bfrag[MTILES * KSLOTS * 32 * 2]; // uint2/slot
__device__ __align__(16) float g_c[Mm];
__device__ __align__(16) float g_partial[MB * Nn];   // [mb][n] coalesced
__device__ unsigned g_mmu[2] = {0u, 0x7f800000u};    // max-bits, min-bits (dist>0)
__device__ int g_cnt = 0;

// ---------------------------------------------------------------------------
__device__ __forceinline__ uint32_t pk(__nv_bfloat16 lo, __nv_bfloat16 hi) {
    __nv_bfloat162 p = __halves2bfloat162(lo, hi);
    return *reinterpret_cast<uint32_t*>(&p);
}
__device__ __forceinline__ void sp(float f, __nv_bfloat16& h, __nv_bfloat16& l) {
    h = __float2bfloat16(f);
    l = __float2bfloat16(f - __bfloat162float(h));
}

// ---------------------------------------------------------------------------
// prep: blocks [0,256) A-frags (hi+lo per thread), [256,384) B-frags,
//       [384,640) bias c. Block 384/tid 0 resets min/max + counter.
// ---------------------------------------------------------------------------
__global__ void prep_kernel(const float* __restrict__ samples,
                            const float* __restrict__ means,
                            const float* __restrict__ stds) {
    int bid = blockIdx.x, tid = threadIdx.x;
    if (bid < 256) {
        int gt = bid * 256 + tid;                 // 0 .. 65535
        int lane = gt & 31, slot = gt >> 5;       // slot: stile*4 + kg
        int kg = slot & 3, stile = slot >> 2;
        int g = lane >> 2, t = lane & 3;
        int kb0 = kg * 16;                        // 0,16,32,48
        bool sq = kb0 >= 32;
        int dbase = (kb0 & 16) + 2 * t;
        int r0 = stile * 16 + g, r1 = r0 + 8;
        float2 p00 = __ldg((const float2*)(samples + r0 * Dd + dbase));
        float2 p01 = __ldg((const float2*)(samples + r0 * Dd + dbase + 8));
        float2 p10 = __ldg((const float2*)(samples + r1 * Dd + dbase));
        float2 p11 = __ldg((const float2*)(samples + r1 * Dd + dbase + 8));
        if (sq) {
            p00.x *= p00.x; p00.y *= p00.y; p01.x *= p01.x; p01.y *= p01.y;
            p10.x *= p10.x; p10.y *= p10.y; p11.x *= p11.x; p11.y *= p11.y;
        }
        __nv_bfloat16 h0,l0,h1,l1,h2,l2,h3,l3,h4,l4,h5,l5,h6,l6,h7,l7;
        sp(p00.x,h0,l0); sp(p00.y,h1,l1); sp(p10.x,h2,l2); sp(p10.y,h3,l3);
        sp(p01.x,h4,l4); sp(p01.y,h5,l5); sp(p11.x,h6,l6); sp(p11.y,h7,l7);
        uint4 vh, vl;
        vh.x = pk(h0,h1); vh.y = pk(h2,h3); vh.z = pk(h4,h5); vh.w = pk(h6,h7);
        vl.x = pk(l0,l1); vl.y = pk(l2,l3); vl.z = pk(l4,l5); vl.w = pk(l6,l7);
        uint4* A4 = (uint4*)g_Afrag;
        int base = (stile * KSLOTS + kg) * 32 + lane;
        A4[base] = vh;
        A4[base + 4 * 32] = vl;
    } else if (bid < 384) {
        int gt = (bid - 256) * 256 + tid;         // 0 .. 32767
        int lane = gt & 31, slot = gt >> 5;       // slot: mtile*4 + kg
        int kg = slot & 3, mtile = slot >> 2;
        int g = lane >> 2, t = lane & 3;
        int kb0 = kg * 16;
        bool isq = kb0 >= 32;
        int dbase = (kb0 & 16) + 2 * t;
        int m = mtile * 8 + g;
        float2 s0 = __ldg((const float2*)(stds + m * Dd + dbase));
        float2 s1 = __ldg((const float2*)(stds + m * Dd + dbase + 8));
        float2 f0, f1;
        if (isq) {
            f0.x = -0.5f / s0.x; f0.y = -0.5f / s0.y;
            f1.x = -0.5f / s1.x; f1.y = -0.5f / s1.y;
        } else {
            float2 m0 = __ldg((const float2*)(means + m * Dd + dbase));
            float2 m1 = __ldg((const float2*)(means + m * Dd + dbase + 8));
            f0.x = m0.x / s0.x; f0.y = m0.y / s0.y;
            f1.x = m1.x / s1.x; f1.y = m1.y / s1.y;
        }
        __nv_bfloat16 h0,l0,h1,l1,h2,l2,h3,l3;
        sp(f0.x,h0,l0); sp(f0.y,h1,l1); sp(f1.x,h2,l2); sp(f1.y,h3,l3);
        uint2 vh, vl;
        vh.x = pk(h0,h1); vh.y = pk(h2,h3);
        vl.x = pk(l0,l1); vl.y = pk(l2,l3);
        uint2* B2 = (uint2*)g_Bfrag;
        int base = (mtile * KSLOTS + kg) * 32 + lane;
        B2[base] = vh;
        B2[base + 4 * 32] = vl;
    } else {
        if (bid == 384 && tid == 0) {             // reset state for this replay
            g_mmu[0] = 0u;
            g_mmu[1] = 0x7f800000u;
            g_cnt = 0;
        }
        int idx = (bid - 384) * 256 + tid;        // M*D
        int m = idx >> 5, d = idx & 31;
        float mean = __ldg(means + m * Dd + d);
        float cp = -0.5f * mean * mean / __ldg(stds + m * Dd + d);
#pragma unroll
        for (int o = 16; o > 0; o >>= 1)
            cp += __shfl_xor_sync(0xffffffffu, cp, o);
        if (d == 0) g_c[m] = cp;
    }
}

// ---------------------------------------------------------------------------
__device__ __forceinline__ void mma16816(float* d, const uint4& a, const uint2& b) {
    asm volatile(
        "mma.sync.aligned.m16n8k16.row.col.f32.bf16.bf16.f32 "
        "{%0,%1,%2,%3}, {%4,%5,%6,%7}, {%8,%9}, {%0,%1,%2,%3};"
        : "+f"(d[0]), "+f"(d[1]), "+f"(d[2]), "+f"(d[3])
        : "r"(a.x), "r"(a.y), "r"(a.z), "r"(a.w), "r"(b.x), "r"(b.y));
}

// ---------------------------------------------------------------------------
// Main: block = 128 samples x 128 means; 8 warps = 2(n) x 4(m); warp 64x32.
// ---------------------------------------------------------------------------
__global__ void __launch_bounds__(256, 2) kde_main() {
    __shared__ float spart[4][128];
    const int tid = threadIdx.x, lane = tid & 31, w = tid >> 5;
    const int wn = w >> 2, wm = w & 3, g = lane >> 2, t = lane & 3;
    const int bx = blockIdx.x, by = blockIdx.y;

    float acc[4][4][4];
#pragma unroll
    for (int mi = 0; mi < 4; mi++)
#pragma unroll
        for (int ni = 0; ni < 4; ni++)
#pragma unroll
            for (int e = 0; e < 4; e++) acc[mi][ni][e] = 0.0f;

    const uint4* __restrict__ Af = (const uint4*)g_Afrag;
    const uint2* __restrict__ Bf = (const uint2*)g_Bfrag;
    const int abase = (bx * 8 + wn * 4) * KSLOTS * 32 + lane;   // + mi*256 + ks*32
    const int bbase = (by * 16 + wm * 4) * KSLOTS * 32 + lane;  // + ni*256 + ks*32

#pragma unroll
    for (int ks = 0; ks < 4; ks++) {
        uint4 ah[4], al[4];
        uint2 bh[4], bl[4];
#pragma unroll
        for (int mi = 0; mi < 4; mi++) {
            ah[mi] = __ldg(Af + abase + mi * 256 + ks * 32);
            al[mi] = __ldg(Af + abase + mi * 256 + (ks + 4) * 32);
        }
#pragma unroll
        for (int ni = 0; ni < 4; ni++) {
            bh[ni] = __ldg(Bf + bbase + ni * 256 + ks * 32);
            bl[ni] = __ldg(Bf + bbase + ni * 256 + (ks + 4) * 32);
        }
#pragma unroll
        for (int mi = 0; mi < 4; mi++)
#pragma unroll
            for (int ni = 0; ni < 4; ni++)
                mma16816(acc[mi][ni], ah[mi], bh[ni]);
#pragma unroll
        for (int mi = 0; mi < 4; mi++)
#pragma unroll
            for (int ni = 0; ni < 4; ni++)
                mma16816(acc[mi][ni], ah[mi], bl[ni]);
#pragma unroll
        for (int mi = 0; mi < 4; mi++)
#pragma unroll
            for (int ni = 0; ni < 4; ni++)
                mma16816(acc[mi][ni], al[mi], bh[ni]);
    }

    // Epilogue: exp(acc + c) and sum over this warp's 32 mean columns.
    const int mcol = by * 128 + wm * 32 + 2 * t;
#pragma unroll
    for (int mi = 0; mi < 4; mi++) {
        float s0 = 0.0f, s1 = 0.0f;
#pragma unroll
        for (int ni = 0; ni < 4; ni++) {
            float2 c = *(const float2*)(g_c + mcol + ni * 8);
            s0 += __expf(acc[mi][ni][0] + c.x) + __expf(acc[mi][ni][1] + c.y);
            s1 += __expf(acc[mi][ni][2] + c.x) + __expf(acc[mi][ni][3] + c.y);
        }
        s0 += __shfl_xor_sync(0xffffffffu, s0, 1);
        s0 += __shfl_xor_sync(0xffffffffu, s0, 2);
        s1 += __shfl_xor_sync(0xffffffffu, s1, 1);
        s1 += __shfl_xor_sync(0xffffffffu, s1, 2);
        if (t == 0) {
            spart[wm][wn * 64 + mi * 16 + g]     = s0;
            spart[wm][wn * 64 + mi * 16 + 8 + g] = s1;
        }
    }
    __syncthreads();
    if (tid < 128) {
        float v = spart[0][tid] + spart[1][tid] + spart[2][tid] + spart[3][tid];
        g_partial[by * Nn + bx * 128 + tid] = v;   // coalesced
    }
}

// ---------------------------------------------------------------------------
// Fused tail: dist (in regs) + deterministic uint atomics + spin grid-sync +
// PARALLEL per-block flip writes. State reset by prep each replay.
// ---------------------------------------------------------------------------
__global__ void tail_fused(float* __restrict__ out) {
    __shared__ float smx[16], smn[16];
    const int tid = threadIdx.x;
    const int n = blockIdx.x * 512 + tid;

    float s = 0.0f;
#pragma unroll
    for (int mb = 0; mb < MB; mb++) s += g_partial[mb * Nn + n];
    float d = s * (1.0f / (float)Mm);

    float mx = d, mn = d;
#pragma unroll
    for (int o = 16; o > 0; o >>= 1) {
        mx = fmaxf(mx, __shfl_xor_sync(0xffffffffu, mx, o));
        mn = fminf(mn, __shfl_xor_sync(0xffffffffu, mn, o));
    }
    int wi = tid >> 5;
    if ((tid & 31) == 0) { smx[wi] = mx; smn[wi] = mn; }
    __syncthreads();
    if (tid == 0) {
        mx = smx[0]; mn = smn[0];
#pragma unroll
        for (int i = 1; i < 16; i++) {
            mx = fmaxf(mx, smx[i]);
            mn = fminf(mn, smn[i]);
        }
        atomicMax(&g_mmu[0], __float_as_uint(mx));   // dist > 0: uint order == float order
        atomicMin(&g_mmu[1], __float_as_uint(mn));
        __threadfence();
        atomicAdd(&g_cnt, 1);
        // spin until all blocks have contributed (all 16 co-resident: safe)
        while (atomicAdd(&g_cnt, 0) < TBLOCKS) { __nanosleep(64); }
    }
    __syncthreads();

    float off = __uint_as_float(atomicAdd(&g_mmu[0], 0u)) +
                __uint_as_float(atomicAdd(&g_mmu[1], 0u));
    out[n] = off - d;
}

// ---------------------------------------------------------------------------
extern "C" void kernel_launch(void* const* d_in, const int* in_sizes, int n_in,
                              void* d_out, int out_size) {
    const float* samples = (const float*)d_in[0];
    const float* means   = (const float*)d_in[1];
    const float* stds    = (const float*)d_in[2];
    float* out = (float*)d_out;

    prep_kernel<<<640, 256>>>(samples, means, stds);
    dim3 grid(Nn / 128, Mm / 128);
    kde_main<<<grid, 256>>>();
    tail_fused<<<TBLOCKS, 512>>>(out);
}

// round 11
// speedup vs baseline: 1.4317x; 1.4317x over previous
#include <cuda_runtime.h>
#include <cuda_bf16.h>
#include <math.h>
#include <stdint.h>

#define Nn 8192
#define Mm 2048
#define Dd 32
#define STILES (Nn / 16)        // 512 sample tiles (m16)
#define MTILES (Mm / 8)         // 256 mean tiles (n8)
#define KSLOTS 8                // 4 hi + 4 lo k16-groups (dedup'd)
#define MB 16                   // mean blocks of 128
#define TBLOCKS 16

// Fragment-layout operands + scratch
__device__ __align__(16) uint32_t g_Afrag[STILES * KSLOTS * 32 * 4]; // uint4/slot
__device__ __align__(16) uint32_t g_Bfrag[MTILES * KSLOTS * 32 * 2]; // uint2/slot
__device__ __align__(16) float g_c[Mm];
__device__ __align__(16) float g_partial[MB * Nn];   // [mb][n] coalesced
__device__ unsigned g_mmu[2] = {0u, 0x7f800000u};    // max-bits, min-bits (dist>0)
__device__ int g_cnt = 0;

// ---------------------------------------------------------------------------
__device__ __forceinline__ uint32_t pk(__nv_bfloat16 lo, __nv_bfloat16 hi) {
    __nv_bfloat162 p = __halves2bfloat162(lo, hi);
    return *reinterpret_cast<uint32_t*>(&p);
}
__device__ __forceinline__ void sp(float f, __nv_bfloat16& h, __nv_bfloat16& l) {
    h = __float2bfloat16(f);
    l = __float2bfloat16(f - __bfloat162float(h));
}
__device__ __forceinline__ unsigned ldcg_u32(const unsigned* p) {
    unsigned v;
    asm volatile("ld.global.cg.u32 %0, [%1];" : "=r"(v) : "l"(p) : "memory");
    return v;
}
__device__ __forceinline__ int ldcg_s32(const int* p) {
    int v;
    asm volatile("ld.global.cg.s32 %0, [%1];" : "=r"(v) : "l"(p) : "memory");
    return v;
}

// ---------------------------------------------------------------------------
// prep: blocks [0,256) A-frags (hi+lo per thread), [256,384) B-frags,
//       [384,640) bias c. Block 384/tid 0 resets min/max + counter.
// ---------------------------------------------------------------------------
__global__ void prep_kernel(const float* __restrict__ samples,
                            const float* __restrict__ means,
                            const float* __restrict__ stds) {
    int bid = blockIdx.x, tid = threadIdx.x;
    if (bid < 256) {
        int gt = bid * 256 + tid;                 // 0 .. 65535
        int lane = gt & 31, slot = gt >> 5;       // slot: stile*4 + kg
        int kg = slot & 3, stile = slot >> 2;
        int g = lane >> 2, t = lane & 3;
        int kb0 = kg * 16;                        // 0,16,32,48
        bool sq = kb0 >= 32;
        int dbase = (kb0 & 16) + 2 * t;
        int r0 = stile * 16 + g, r1 = r0 + 8;
        float2 p00 = __ldg((const float2*)(samples + r0 * Dd + dbase));
        float2 p01 = __ldg((const float2*)(samples + r0 * Dd + dbase + 8));
        float2 p10 = __ldg((const float2*)(samples + r1 * Dd + dbase));
        float2 p11 = __ldg((const float2*)(samples + r1 * Dd + dbase + 8));
        if (sq) {
            p00.x *= p00.x; p00.y *= p00.y; p01.x *= p01.x; p01.y *= p01.y;
            p10.x *= p10.x; p10.y *= p10.y; p11.x *= p11.x; p11.y *= p11.y;
        }
        __nv_bfloat16 h0,l0,h1,l1,h2,l2,h3,l3,h4,l4,h5,l5,h6,l6,h7,l7;
        sp(p00.x,h0,l0); sp(p00.y,h1,l1); sp(p10.x,h2,l2); sp(p10.y,h3,l3);
        sp(p01.x,h4,l4); sp(p01.y,h5,l5); sp(p11.x,h6,l6); sp(p11.y,h7,l7);
        uint4 vh, vl;
        vh.x = pk(h0,h1); vh.y = pk(h2,h3); vh.z = pk(h4,h5); vh.w = pk(h6,h7);
        vl.x = pk(l0,l1); vl.y = pk(l2,l3); vl.z = pk(l4,l5); vl.w = pk(l6,l7);
        uint4* A4 = (uint4*)g_Afrag;
        int base = (stile * KSLOTS + kg) * 32 + lane;
        A4[base] = vh;
        A4[base + 4 * 32] = vl;
    } else if (bid < 384) {
        int gt = (bid - 256) * 256 + tid;         // 0 .. 32767
        int lane = gt & 31, slot = gt >> 5;       // slot: mtile*4 + kg
        int kg = slot & 3, mtile = slot >> 2;
        int g = lane >> 2, t = lane & 3;
        int kb0 = kg * 16;
        bool isq = kb0 >= 32;
        int dbase = (kb0 & 16) + 2 * t;
        int m = mtile * 8 + g;
        float2 s0 = __ldg((const float2*)(stds + m * Dd + dbase));
        float2 s1 = __ldg((const float2*)(stds + m * Dd + dbase + 8));
        float2 f0, f1;
        if (isq) {
            f0.x = -0.5f / s0.x; f0.y = -0.5f / s0.y;
            f1.x = -0.5f / s1.x; f1.y = -0.5f / s1.y;
        } else {
            float2 m0 = __ldg((const float2*)(means + m * Dd + dbase));
            float2 m1 = __ldg((const float2*)(means + m * Dd + dbase + 8));
            f0.x = m0.x / s0.x; f0.y = m0.y / s0.y;
            f1.x = m1.x / s1.x; f1.y = m1.y / s1.y;
        }
        __nv_bfloat16 h0,l0,h1,l1,h2,l2,h3,l3;
        sp(f0.x,h0,l0); sp(f0.y,h1,l1); sp(f1.x,h2,l2); sp(f1.y,h3,l3);
        uint2 vh, vl;
        vh.x = pk(h0,h1); vh.y = pk(h2,h3);
        vl.x = pk(l0,l1); vl.y = pk(l2,l3);
        uint2* B2 = (uint2*)g_Bfrag;
        int base = (mtile * KSLOTS + kg) * 32 + lane;
        B2[base] = vh;
        B2[base + 4 * 32] = vl;
    } else {
        if (bid == 384 && tid == 0) {             // reset state for this replay
            g_mmu[0] = 0u;
            g_mmu[1] = 0x7f800000u;
            g_cnt = 0;
        }
        int idx = (bid - 384) * 256 + tid;        // M*D
        int m = idx >> 5, d = idx & 31;
        float mean = __ldg(means + m * Dd + d);
        float cp = -0.5f * mean * mean / __ldg(stds + m * Dd + d);
#pragma unroll
        for (int o = 16; o > 0; o >>= 1)
            cp += __shfl_xor_sync(0xffffffffu, cp, o);
        if (d == 0) g_c[m] = cp;
    }
}

// ---------------------------------------------------------------------------
__device__ __forceinline__ void mma16816(float* d, const uint4& a, const uint2& b) {
    asm volatile(
        "mma.sync.aligned.m16n8k16.row.col.f32.bf16.bf16.f32 "
        "{%0,%1,%2,%3}, {%4,%5,%6,%7}, {%8,%9}, {%0,%1,%2,%3};"
        : "+f"(d[0]), "+f"(d[1]), "+f"(d[2]), "+f"(d[3])
        : "r"(a.x), "r"(a.y), "r"(a.z), "r"(a.w), "r"(b.x), "r"(b.y));
}

// ---------------------------------------------------------------------------
// Main: block = 128 samples x 128 means; 8 warps = 2(n) x 4(m); warp 64x32.
// ---------------------------------------------------------------------------
__global__ void __launch_bounds__(256, 2) kde_main() {
    __shared__ float spart[4][128];
    const int tid = threadIdx.x, lane = tid & 31, w = tid >> 5;
    const int wn = w >> 2, wm = w & 3, g = lane >> 2, t = lane & 3;
    const int bx = blockIdx.x, by = blockIdx.y;

    float acc[4][4][4];
#pragma unroll
    for (int mi = 0; mi < 4; mi++)
#pragma unroll
        for (int ni = 0; ni < 4; ni++)
#pragma unroll
            for (int e = 0; e < 4; e++) acc[mi][ni][e] = 0.0f;

    const uint4* __restrict__ Af = (const uint4*)g_Afrag;
    const uint2* __restrict__ Bf = (const uint2*)g_Bfrag;
    const int abase = (bx * 8 + wn * 4) * KSLOTS * 32 + lane;   // + mi*256 + ks*32
    const int bbase = (by * 16 + wm * 4) * KSLOTS * 32 + lane;  // + ni*256 + ks*32

#pragma unroll
    for (int ks = 0; ks < 4; ks++) {
        uint4 ah[4], al[4];
        uint2 bh[4], bl[4];
#pragma unroll
        for (int mi = 0; mi < 4; mi++) {
            ah[mi] = __ldg(Af + abase + mi * 256 + ks * 32);
            al[mi] = __ldg(Af + abase + mi * 256 + (ks + 4) * 32);
        }
#pragma unroll
        for (int ni = 0; ni < 4; ni++) {
            bh[ni] = __ldg(Bf + bbase + ni * 256 + ks * 32);
            bl[ni] = __ldg(Bf + bbase + ni * 256 + (ks + 4) * 32);
        }
#pragma unroll
        for (int mi = 0; mi < 4; mi++)
#pragma unroll
            for (int ni = 0; ni < 4; ni++)
                mma16816(acc[mi][ni], ah[mi], bh[ni]);
#pragma unroll
        for (int mi = 0; mi < 4; mi++)
#pragma unroll
            for (int ni = 0; ni < 4; ni++)
                mma16816(acc[mi][ni], ah[mi], bl[ni]);
#pragma unroll
        for (int mi = 0; mi < 4; mi++)
#pragma unroll
            for (int ni = 0; ni < 4; ni++)
                mma16816(acc[mi][ni], al[mi], bh[ni]);
    }

    // Epilogue: exp(acc + c) and sum over this warp's 32 mean columns.
    const int mcol = by * 128 + wm * 32 + 2 * t;
#pragma unroll
    for (int mi = 0; mi < 4; mi++) {
        float s0 = 0.0f, s1 = 0.0f;
#pragma unroll
        for (int ni = 0; ni < 4; ni++) {
            float2 c = *(const float2*)(g_c + mcol + ni * 8);
            s0 += __expf(acc[mi][ni][0] + c.x) + __expf(acc[mi][ni][1] + c.y);
            s1 += __expf(acc[mi][ni][2] + c.x) + __expf(acc[mi][ni][3] + c.y);
        }
        s0 += __shfl_xor_sync(0xffffffffu, s0, 1);
        s0 += __shfl_xor_sync(0xffffffffu, s0, 2);
        s1 += __shfl_xor_sync(0xffffffffu, s1, 1);
        s1 += __shfl_xor_sync(0xffffffffu, s1, 2);
        if (t == 0) {
            spart[wm][wn * 64 + mi * 16 + g]     = s0;
            spart[wm][wn * 64 + mi * 16 + 8 + g] = s1;
        }
    }
    __syncthreads();
    if (tid < 128) {
        float v = spart[0][tid] + spart[1][tid] + spart[2][tid] + spart[3][tid];
        g_partial[by * Nn + bx * 128 + tid] = v;   // coalesced
    }
}

// ---------------------------------------------------------------------------
// Fused tail: dist in regs; 2 uint atomics/block; tid0 spin on plain ld.cg;
// broadcast ld.cg reads of min/max; parallel per-block writes.
// ---------------------------------------------------------------------------
__global__ void tail_fused(float* __restrict__ out) {
    __shared__ float smx[16], smn[16];
    const int tid = threadIdx.x;
    const int n = blockIdx.x * 512 + tid;

    float s = 0.0f;
#pragma unroll
    for (int mb = 0; mb < MB; mb++) s += g_partial[mb * Nn + n];
    float d = s * (1.0f / (float)Mm);

    float mx = d, mn = d;
#pragma unroll
    for (int o = 16; o > 0; o >>= 1) {
        mx = fmaxf(mx, __shfl_xor_sync(0xffffffffu, mx, o));
        mn = fminf(mn, __shfl_xor_sync(0xffffffffu, mn, o));
    }
    int wi = tid >> 5;
    if ((tid & 31) == 0) { smx[wi] = mx; smn[wi] = mn; }
    __syncthreads();
    if (tid == 0) {
        mx = smx[0]; mn = smn[0];
#pragma unroll
        for (int i = 1; i < 16; i++) {
            mx = fmaxf(mx, smx[i]);
            mn = fminf(mn, smn[i]);
        }
        atomicMax(&g_mmu[0], __float_as_uint(mx));   // dist > 0: uint order == float order
        atomicMin(&g_mmu[1], __float_as_uint(mn));
        __threadfence();
        atomicAdd(&g_cnt, 1);
        // spin on a PLAIN L2 load (not an atomic) until all 16 blocks arrive
        while (ldcg_s32(&g_cnt) < TBLOCKS) { }
    }
    __syncthreads();

    // broadcast loads (no serialization); atomics completed at L2 before cnt hit 16
    float off = __uint_as_float(ldcg_u32(&g_mmu[0])) +
                __uint_as_float(ldcg_u32(&g_mmu[1]));
    out[n] = off - d;
}

// ---------------------------------------------------------------------------
extern "C" void kernel_launch(void* const* d_in, const int* in_sizes, int n_in,
                              void* d_out, int out_size) {
    const float* samples = (const float*)d_in[0];
    const float* means   = (const float*)d_in[1];
    const float* stds    = (const float*)d_in[2];
    float* out = (float*)d_out;

    prep_kernel<<<640, 256>>>(samples, means, stds);
    dim3 grid(Nn / 128, Mm / 128);
    kde_main<<<grid, 256>>>();
    tail_fused<<<TBLOCKS, 512>>>(out);
}